// round 15
// baseline (speedup 1.0000x reference)
#include <cuda_runtime.h>
#include <cuda_bf16.h>
#include <cuda_fp16.h>
#include <mma.h>
#include <cuda_pipeline.h>
#include <math.h>
#include <stdint.h>

using namespace nvcuda;

#define BB 4
#define CC 256
#define HW 4096
#define CK 2304
#define CPG 8
#define NPIX 16384
#define LDA 72                           /* 64 + 8 pad */
#define LDB 136                          /* 128 + 8 pad */
#define A_STRIDE (256*LDA)               /* 18432 halves per A stage */
#define B_BASE   (2*A_STRIDE)            /* 36864 */
#define B_STRIDE (64*LDB)                /* 8704 halves per B stage */
#define SMEM_GEMM 131072                 /* epilogue 256x128 fp32 dominates */

// ---------------- scratch (device globals; no allocations) ----------------
__device__ __align__(128) float g_h  [(size_t)BB*CC*HW];
__device__ __align__(128) float g_f  [(size_t)BB*CC*HW];
__device__ __align__(128) float g_off[(size_t)BB*18*HW];
__device__ __align__(128) float g_h2 [(size_t)BB*CC*HW];
__device__ __align__(128) __half g_w [(size_t)CC*CK];     // [O][k*256+c], fp16

// ---------------- GroupNorm + ReLU (in: x or g_h2; out: g_h) ----------------
__global__ void gn_relu_kernel(const float* __restrict__ inp,
                               const float* __restrict__ gamma,
                               const float* __restrict__ beta) {
    const float* in = inp ? inp : (const float*)g_h2;
    int b = blockIdx.x >> 5, g = blockIdx.x & 31;
    size_t base = ((size_t)b*CC + g*CPG) * HW;
    const float4* p4 = (const float4*)(in + base);
    const int N4 = CPG*HW/4;
    float s = 0.f, s2 = 0.f;
    for (int i = threadIdx.x; i < N4; i += 256) {
        float4 v = p4[i];
        s  += v.x + v.y + v.z + v.w;
        s2 += v.x*v.x + v.y*v.y + v.z*v.z + v.w*v.w;
    }
    #pragma unroll
    for (int o = 16; o; o >>= 1) {
        s  += __shfl_xor_sync(0xffffffffu, s,  o);
        s2 += __shfl_xor_sync(0xffffffffu, s2, o);
    }
    __shared__ float sh[16];
    __shared__ float stats[2];
    int wid = threadIdx.x >> 5, lane = threadIdx.x & 31;
    if (lane == 0) { sh[wid] = s; sh[8 + wid] = s2; }
    __syncthreads();
    if (threadIdx.x == 0) {
        float ts = 0.f, ts2 = 0.f;
        #pragma unroll
        for (int i = 0; i < 8; i++) { ts += sh[i]; ts2 += sh[8+i]; }
        const float invN = 1.f / (float)(CPG*HW);
        float mean = ts * invN;
        float var  = ts2 * invN - mean*mean;
        stats[0] = mean;
        stats[1] = rsqrtf(var + 1e-5f);
    }
    __syncthreads();
    float mean = stats[0], inv = stats[1];
    float4* o4 = (float4*)(g_h + base);
    for (int i = threadIdx.x; i < N4; i += 256) {
        int c = g*CPG + (i >> 10);
        float ga = gamma[c] * inv;
        float be = beta[c] - mean * ga;
        float4 v = p4[i];
        v.x = fmaxf(fmaf(v.x, ga, be), 0.f);
        v.y = fmaxf(fmaf(v.y, ga, be), 0.f);
        v.z = fmaxf(fmaf(v.z, ga, be), 0.f);
        v.w = fmaxf(fmaf(v.w, ga, be), 0.f);
        o4[i] = v;
    }
}

// ---------------- Depthwise 7x7 SAME (g_h -> g_f) ----------------
__global__ void dw_conv_kernel(const float* __restrict__ wts) {
    int bc = blockIdx.x;
    int c = bc & (CC - 1);
    const float* p = g_h + (size_t)bc * HW;
    __shared__ float tile[70*70];
    __shared__ float wk[49];
    if (threadIdx.x < 49) wk[threadIdx.x] = wts[c*49 + threadIdx.x];
    for (int i = threadIdx.x; i < 70*70; i += 256) {
        int ty = i / 70 - 3, tx = i % 70 - 3;
        tile[i] = (ty >= 0 && ty < 64 && tx >= 0 && tx < 64) ? p[ty*64 + tx] : 0.f;
    }
    __syncthreads();
    int xg = (threadIdx.x & 15) * 4;
    int yb = threadIdx.x >> 4;
    #pragma unroll
    for (int it = 0; it < 4; it++) {
        int oy = it*16 + yb;
        float a0 = 0.f, a1 = 0.f, a2 = 0.f, a3 = 0.f;
        #pragma unroll
        for (int dy = 0; dy < 7; dy++) {
            const float* r = &tile[(oy+dy)*70 + xg];
            #pragma unroll
            for (int dx = 0; dx < 7; dx++) {
                float wv = wk[dy*7 + dx];
                a0 = fmaf(r[dx+0], wv, a0);
                a1 = fmaf(r[dx+1], wv, a1);
                a2 = fmaf(r[dx+2], wv, a2);
                a3 = fmaf(r[dx+3], wv, a3);
            }
        }
        float4 o4 = make_float4(a0, a1, a2, a3);
        *(float4*)&g_f[(size_t)bc*HW + oy*64 + xg] = o4;
    }
}

// ---------------- Pointwise 1x1 + bias (g_f -> g_off) ----------------
__global__ void pw_kernel(const float* __restrict__ pw,
                          const float* __restrict__ pwb) {
    int b = blockIdx.x >> 4;
    int p = (blockIdx.x & 15) * 256 + threadIdx.x;
    __shared__ float wsh[18*256];
    for (int i = threadIdx.x; i < 18*256; i += 256) wsh[i] = pw[i];
    __syncthreads();
    float acc[18];
    #pragma unroll
    for (int o = 0; o < 18; o++) acc[o] = 0.f;
    const float* fb = g_f + (size_t)b*CC*HW + p;
    for (int c = 0; c < CC; c++) {
        float v = fb[(size_t)c*HW];
        #pragma unroll
        for (int o = 0; o < 18; o++) acc[o] = fmaf(v, wsh[o*256 + c], acc[o]);
    }
    #pragma unroll
    for (int o = 0; o < 18; o++)
        g_off[((size_t)b*18 + o)*HW + p] = acc[o] + pwb[o];
}

// ---------------- weight repack: [O][c*9+k] fp32 -> [O][k*256+c] fp16 ----------------
__global__ void repack_w_kernel(const float* __restrict__ w) {
    int idx = blockIdx.x*256 + threadIdx.x;
    int o = idx / CK;
    int rem = idx - o*CK;
    int c = rem / 9;
    int k = rem - c*9;
    g_w[o*CK + k*256 + c] = __float2half(w[idx]);
}

// ---------------- fused im2col + WMMA fp16 GEMM ----------------
// C[o,p] = sum_ck W[o,ck] * gather(x)[ck,p]; BM=256, BN=128 pixels, BK=64
// 512 threads = 16 warps (4x4); warp tile 64x32 -> acc[4][2]
// A: cp.async double buffer. B: built in-kernel (bilinear gather -> fp16 smem).
__device__ __forceinline__ unsigned int pack_h2(__half a, __half b) {
    return (unsigned int)__half_as_ushort(a) |
           ((unsigned int)__half_as_ushort(b) << 16);
}

__global__ void __launch_bounds__(512, 1) fused_gemm_kernel(
        const float* __restrict__ bias,
        const float* __restrict__ res,     // null or x (residual)
        float* __restrict__ outp) {        // null -> write g_h2
    extern __shared__ __align__(16) char smem[];
    __half* sm = (__half*)smem;
    int tid = threadIdx.x;
    int warp = tid >> 5;
    int wm = warp & 3;      // 0..3 -> 64-row tiles
    int wn = warp >> 2;     // 0..3 -> 32-col tiles
    int bn = blockIdx.x * 128;            // global pixel base
    int b  = bn >> 12;
    int pin = bn & 4095;
    float* out = outp ? outp : (float*)g_h2;
    const float* xb = g_h + (size_t)b*CC*HW;

    // producer mapping: tp -> pixel pair, tc -> 8-channel group within chunk
    int tp = tid & 63;
    int tc = tid >> 6;     // 0..7
    int p0 = pin + tp*2;   // local pixel index of first of the pair

    wmma::fragment<wmma::accumulator, 16, 16, 16, float> acc[4][2];
    #pragma unroll
    for (int i = 0; i < 4; i++)
        #pragma unroll
        for (int j = 0; j < 2; j++)
            wmma::fill_fragment(acc[i][j], 0.f);

    // per-thread gather metadata for current kernel-offset k (2 pixels)
    int   gidx[2][4];
    float gwgt[2][4];
    auto compute_meta = [&](int k) {
        float ky = (float)(k/3 - 1), kx = (float)(k%3 - 1);
        #pragma unroll
        for (int e = 0; e < 2; e++) {
            int p = p0 + e;
            int yi = p >> 6, xi = p & 63;
            float offy = g_off[((size_t)b*18 + 2*k    )*HW + p];
            float offx = g_off[((size_t)b*18 + 2*k + 1)*HW + p];
            float py = (float)yi + ky + offy;
            float px = (float)xi + kx + offx;
            float y0f = floorf(py), x0f = floorf(px);
            float wy1 = py - y0f, wx1 = px - x0f;
            float wy0 = 1.f - wy1, wx0 = 1.f - wx1;
            float y1f = y0f + 1.f, x1f = x0f + 1.f;
            bool vy0 = (y0f >= 0.f) && (y0f <= 63.f);
            bool vy1 = (y1f >= 0.f) && (y1f <= 63.f);
            bool vx0 = (x0f >= 0.f) && (x0f <= 63.f);
            bool vx1 = (x1f >= 0.f) && (x1f <= 63.f);
            gwgt[e][0] = (vy0 && vx0) ? wy0*wx0 : 0.f;
            gwgt[e][1] = (vy0 && vx1) ? wy0*wx1 : 0.f;
            gwgt[e][2] = (vy1 && vx0) ? wy1*wx0 : 0.f;
            gwgt[e][3] = (vy1 && vx1) ? wy1*wx1 : 0.f;
            int yc0 = min(max((int)y0f, 0), 63);
            int yc1 = min(max((int)y1f, 0), 63);
            int xc0 = min(max((int)x0f, 0), 63);
            int xc1 = min(max((int)x1f, 0), 63);
            gidx[e][0] = yc0*64 + xc0;
            gidx[e][1] = yc0*64 + xc1;
            gidx[e][2] = yc1*64 + xc0;
            gidx[e][3] = yc1*64 + xc1;
        }
    };

    // A loader: 2048 16B-chunks per stage (256 rows x 64 cols), 4 per thread
    auto load_A = [&](int buf, int kt) {
        __half* sa = sm + buf * A_STRIDE;
        int ko = kt * 64;
        #pragma unroll
        for (int u = 0; u < 4; u++) {
            int i = tid + u*512;
            int row = i >> 3;            // 0..255
            int c8 = (i & 7) * 8;        // 0..56
            __pipeline_memcpy_async(sa + row*LDA + c8,
                                    g_w + (size_t)row*CK + ko + c8, 16);
        }
        __pipeline_commit();
    };

    // B builder: gather 64 channels x 128 pixels into buffer
    auto build_B = [&](int buf, int kt) {
        __half* sB = sm + B_BASE + buf * B_STRIDE;
        int cbase = (kt & 3) * 64;
        #pragma unroll
        for (int j = 0; j < 8; j++) {
            int crow = tc*8 + j;                 // 0..63 within chunk
            const float* pl = xb + (size_t)(cbase + crow)*HW;
            float v0 = gwgt[0][0]*pl[gidx[0][0]];
            v0 = fmaf(gwgt[0][1], pl[gidx[0][1]], v0);
            v0 = fmaf(gwgt[0][2], pl[gidx[0][2]], v0);
            v0 = fmaf(gwgt[0][3], pl[gidx[0][3]], v0);
            float v1 = gwgt[1][0]*pl[gidx[1][0]];
            v1 = fmaf(gwgt[1][1], pl[gidx[1][1]], v1);
            v1 = fmaf(gwgt[1][2], pl[gidx[1][2]], v1);
            v1 = fmaf(gwgt[1][3], pl[gidx[1][3]], v1);
            *(unsigned int*)(sB + crow*LDB + tp*2) =
                pack_h2(__float2half(v0), __float2half(v1));
        }
    };

    // prologue: A[0] async, meta(k=0), B[0]
    load_A(0, 0);
    compute_meta(0);
    build_B(0, 0);
    __pipeline_wait_prior(0);
    __syncthreads();

    const int NK = CK / 64;    // 36 chunks; 4 chunks per kernel-offset k
    for (int kt = 0; kt < NK; kt++) {
        int s = kt & 1;
        if (kt + 1 < NK) {
            load_A(s ^ 1, kt + 1);
            __pipeline_wait_prior(1);      // A[kt] ready
        } else {
            __pipeline_wait_prior(0);
        }

        // MMA on buffers s
        __half* sa = sm + s * A_STRIDE;
        __half* sB = sm + B_BASE + s * B_STRIDE;
        #pragma unroll
        for (int kk = 0; kk < 64; kk += 16) {
            wmma::fragment<wmma::matrix_b, 16, 16, 16, __half, wmma::row_major> fb[2];
            #pragma unroll
            for (int j = 0; j < 2; j++)
                wmma::load_matrix_sync(fb[j], sB + kk*LDB + wn*32 + j*16, LDB);
            #pragma unroll
            for (int i = 0; i < 4; i++) {
                wmma::fragment<wmma::matrix_a, 16, 16, 16, __half, wmma::row_major> fa;
                wmma::load_matrix_sync(fa, sa + (wm*64 + i*16)*LDA + kk, LDA);
                #pragma unroll
                for (int j = 0; j < 2; j++)
                    wmma::mma_sync(acc[i][j], fa, fb[j], acc[i][j]);
            }
        }

        // build next B while (other warps') MMAs drain
        if (kt + 1 < NK) {
            int nxt = kt + 1;
            if ((nxt & 3) == 0) compute_meta(nxt >> 2);
            build_B(s ^ 1, nxt);
        }
        __syncthreads();
    }

    // epilogue: park accumulators in smem (256x128 fp32 = 128KB), fused bias/residual
    float* sOut = (float*)smem;
    #pragma unroll
    for (int i = 0; i < 4; i++)
        #pragma unroll
        for (int j = 0; j < 2; j++)
            wmma::store_matrix_sync(sOut + (wm*64 + i*16)*128 + (wn*32 + j*16),
                                    acc[i][j], 128, wmma::mem_row_major);
    __syncthreads();

    int r0 = tid >> 5;            // 0..15
    int c4 = (tid & 31) * 4;      // 0..124
    #pragma unroll
    for (int i = 0; i < 16; i++) {
        int o = r0 + i*16;        // output channel 0..255
        float4 v = *(float4*)(sOut + o*128 + c4);
        float bs = bias[o];
        v.x += bs; v.y += bs; v.z += bs; v.w += bs;
        size_t off = ((size_t)(b*256 + o))*4096 + pin + c4;
        if (res) {
            float4 rr = *(const float4*)(res + off);
            v.x += rr.x; v.y += rr.y; v.z += rr.z; v.w += rr.w;
        }
        *(float4*)(out + off) = v;
    }
}

// ---------------- launch ----------------
extern "C" void kernel_launch(void* const* d_in, const int* in_sizes, int n_in,
                              void* d_out, int out_size) {
    const float* x    = (const float*)d_in[0];
    const float* gn1g = (const float*)d_in[1];
    const float* gn1b = (const float*)d_in[2];
    const float* dw1  = (const float*)d_in[3];
    const float* pw1  = (const float*)d_in[4];
    const float* pwb1 = (const float*)d_in[5];
    const float* w1   = (const float*)d_in[6];
    const float* b1   = (const float*)d_in[7];
    const float* gn2g = (const float*)d_in[8];
    const float* gn2b = (const float*)d_in[9];
    const float* dw2  = (const float*)d_in[10];
    const float* pw2  = (const float*)d_in[11];
    const float* pwb2 = (const float*)d_in[12];
    const float* w2   = (const float*)d_in[13];
    const float* b2   = (const float*)d_in[14];
    float* out = (float*)d_out;

    cudaFuncSetAttribute(fused_gemm_kernel, cudaFuncAttributeMaxDynamicSharedMemorySize, SMEM_GEMM);

    // stage 1
    gn_relu_kernel<<<128, 256>>>(x, gn1g, gn1b);
    dw_conv_kernel<<<BB*CC, 256>>>(dw1);
    pw_kernel<<<64, 256>>>(pw1, pwb1);
    repack_w_kernel<<<CC*CK/256, 256>>>(w1);
    fused_gemm_kernel<<<128, 512, SMEM_GEMM>>>(b1, nullptr, nullptr);

    // stage 2
    gn_relu_kernel<<<128, 256>>>(nullptr, gn2g, gn2b);
    dw_conv_kernel<<<BB*CC, 256>>>(dw2);
    pw_kernel<<<64, 256>>>(pw2, pwb2);
    repack_w_kernel<<<CC*CK/256, 256>>>(w2);
    fused_gemm_kernel<<<128, 512, SMEM_GEMM>>>(b2, x, out);
}